// round 1
// baseline (speedup 1.0000x reference)
#include <cuda_runtime.h>

#define HNUM 12
#define DHEAD 64
#define BATCH 4
#define LQ 512
#define LK 512
#define DMODEL 768

// ---------------- scratch (device globals; no runtime alloc) ----------------
__device__ float g_Q[BATCH*HNUM*LQ*DHEAD];
__device__ float g_K[BATCH*HNUM*LK*DHEAD];
__device__ float g_V[BATCH*HNUM*LK*DHEAD];
__device__ float g_lnk[3*DHEAD];
__device__ float g_lnv[3*DHEAD];
__device__ float g_qdp[BATCH*HNUM*LQ*4];

// ---------------- K1: layernorm the 3+3 relation embedding rows -------------
__global__ void ln_prep_kernel(const float* __restrict__ dpk, const float* __restrict__ dpv,
                               const float* __restrict__ kg, const float* __restrict__ kb,
                               const float* __restrict__ vg, const float* __restrict__ vb) {
    int w = threadIdx.x >> 5;
    int lane = threadIdx.x & 31;
    if (w >= 6) return;
    const float* src = (w < 3) ? dpk + w * DHEAD : dpv + (w - 3) * DHEAD;
    const float* g   = (w < 3) ? kg : vg;
    const float* be  = (w < 3) ? kb : vb;
    float* dst       = (w < 3) ? g_lnk + w * DHEAD : g_lnv + (w - 3) * DHEAD;
    float e0 = src[lane], e1 = src[lane + 32];
    float s = e0 + e1;
    #pragma unroll
    for (int o = 16; o; o >>= 1) s += __shfl_xor_sync(0xffffffffu, s, o);
    float mu = s * (1.0f / 64.0f);
    float d0 = e0 - mu, d1 = e1 - mu;
    float v = d0 * d0 + d1 * d1;
    #pragma unroll
    for (int o = 16; o; o >>= 1) v += __shfl_xor_sync(0xffffffffu, v, o);
    float rs = rsqrtf(v * (1.0f / 64.0f) + 1e-5f);
    dst[lane]      = d0 * rs * g[lane]      + be[lane];
    dst[lane + 32] = d1 * rs * g[lane + 32] + be[lane + 32];
}

// ---------------- K2: QKV projection GEMMs -----------------------------------
// grid: (12 heads = N-tiles of 64, 32 M-tiles of 64, 3 matrices), 256 threads
__global__ __launch_bounds__(256) void qkv_gemm_kernel(
    const float* __restrict__ hidden, const float* __restrict__ ctx,
    const float* __restrict__ Wq, const float* __restrict__ bq,
    const float* __restrict__ Wk, const float* __restrict__ bk,
    const float* __restrict__ Wv, const float* __restrict__ bv) {
    __shared__ float As[64][16];
    __shared__ float Bs[16][64];
    int sel = blockIdx.z;
    const float* X    = (sel == 0) ? hidden : ctx;
    const float* W    = (sel == 0) ? Wq : (sel == 1 ? Wk : Wv);
    const float* bias = (sel == 0) ? bq : (sel == 1 ? bk : bv);
    float* Out        = (sel == 0) ? g_Q : (sel == 1 ? g_K : g_V);

    int head = blockIdx.x;
    int m0 = blockIdx.y * 64;
    int n0 = head * 64;
    int t = threadIdx.x;

    int ar = t >> 2;            // 0..63  A row
    int ak = (t & 3) << 2;      // 0,4,8,12 A k-col (float4)
    int bkk = t >> 4;           // 0..15 B k-row
    int bc = (t & 15) << 2;     // B col (float4)
    int row_base = (t >> 4) << 2;
    int col_base = (t & 15) << 2;

    float acc[4][4] = {};
    for (int k0 = 0; k0 < DMODEL; k0 += 16) {
        float4 av = *(const float4*)&X[(size_t)(m0 + ar) * DMODEL + k0 + ak];
        *(float4*)&As[ar][ak] = av;
        float4 bw = *(const float4*)&W[(size_t)(k0 + bkk) * DMODEL + n0 + bc];
        *(float4*)&Bs[bkk][bc] = bw;
        __syncthreads();
        #pragma unroll
        for (int kk = 0; kk < 16; kk++) {
            float4 b4 = *(float4*)&Bs[kk][col_base];
            float a0 = As[row_base + 0][kk];
            float a1 = As[row_base + 1][kk];
            float a2 = As[row_base + 2][kk];
            float a3 = As[row_base + 3][kk];
            acc[0][0] += a0 * b4.x; acc[0][1] += a0 * b4.y; acc[0][2] += a0 * b4.z; acc[0][3] += a0 * b4.w;
            acc[1][0] += a1 * b4.x; acc[1][1] += a1 * b4.y; acc[1][2] += a1 * b4.z; acc[1][3] += a1 * b4.w;
            acc[2][0] += a2 * b4.x; acc[2][1] += a2 * b4.y; acc[2][2] += a2 * b4.z; acc[2][3] += a2 * b4.w;
            acc[3][0] += a3 * b4.x; acc[3][1] += a3 * b4.y; acc[3][2] += a3 * b4.z; acc[3][3] += a3 * b4.w;
        }
        __syncthreads();
    }
    #pragma unroll
    for (int i = 0; i < 4; i++) {
        int m = m0 + row_base + i;
        int bb = m >> 9, l = m & 511;
        float* orow = Out + ((size_t)(bb * HNUM + head) * 512 + l) * DHEAD;
        #pragma unroll
        for (int j = 0; j < 4; j++)
            orow[col_base + j] = acc[i][j] + bias[n0 + col_base + j];
    }
}

// ---------------- K3: qdp[b,h,q,r] = Q[b,h,q,:] . lnk[r,:] -------------------
__global__ void qdp_kernel() {
    int w = (blockIdx.x * blockDim.x + threadIdx.x) >> 5;
    int lane = threadIdx.x & 31;
    if (w >= BATCH * HNUM * LQ) return;
    float q0 = g_Q[(size_t)w * 64 + lane];
    float q1 = g_Q[(size_t)w * 64 + lane + 32];
    #pragma unroll
    for (int r = 0; r < 3; r++) {
        float s = q0 * g_lnk[r * 64 + lane] + q1 * g_lnk[r * 64 + lane + 32];
        #pragma unroll
        for (int o = 16; o; o >>= 1) s += __shfl_xor_sync(0xffffffffu, s, o);
        if (lane == 0) g_qdp[w * 4 + r] = s;
    }
    if (lane == 0) g_qdp[w * 4 + 3] = 0.f;
}

// ---------------- K4: fused attention ----------------------------------------
// grid (16 q-tiles, 48 bh), 256 threads, TQ=32 queries per CTA, full 512-key rows
#define TQ 32
#define ATTN_SMEM_BYTES (4*(TQ*512 + TQ*64 + 64*65 + 512 + TQ*4 + TQ*4 + TQ) + TQ*512)

__global__ __launch_bounds__(256, 2) void attn_kernel(
    const float* __restrict__ mask, const int* __restrict__ arc,
    float* __restrict__ out) {
    extern __shared__ char smem_raw[];
    float* sS    = (float*)smem_raw;        // TQ*512  unnormalized scores -> probs
    float* sQ    = sS + TQ * 512;           // TQ*64
    float* sK    = sQ + TQ * 64;            // 64*65 (padded; reused for V)
    float* sMask = sK + 64 * 65;            // 512
    float* sQdp  = sMask + 512;             // TQ*4
    float* sPw   = sQdp + TQ * 4;           // TQ*4
    float* sInv  = sPw + TQ * 4;            // TQ
    unsigned char* sArc = (unsigned char*)(sInv + TQ);  // TQ*512

    int bh = blockIdx.y;
    int b = bh / HNUM, h = bh % HNUM;
    int q0 = blockIdx.x * TQ;
    int t = threadIdx.x;

    const float* Qbase = g_Q + ((size_t)bh * 512 + q0) * 64;
    const float* Kbase = g_K + (size_t)bh * 512 * 64;
    const float* Vbase = g_V + (size_t)bh * 512 * 64;

    for (int i = t; i < TQ * 64; i += 256) sQ[i] = Qbase[i];
    for (int i = t; i < TQ * 4; i += 256) {
        int q = i >> 2, r = i & 3;
        sQdp[i] = (r < 3) ? g_qdp[((size_t)bh * 512 + q0 + q) * 4 + r] : 0.f;
    }
    for (int i = t; i < 512; i += 256) sMask[i] = mask[b * 512 + i];

    int qb = (t >> 5) << 2;   // query group base: 0,4,...,28 (const per warp)
    int l  = t & 31;

    // ---- Pass 1: S = QK^T/8 + qdp[arc] + mask ----
    for (int kt = 0; kt < 8; kt++) {
        __syncthreads();
        for (int i = t; i < 64 * 16; i += 256) {
            int k = i >> 4, d4 = (i & 15) << 2;
            float4 v = *(const float4*)&Kbase[(size_t)(kt * 64 + k) * 64 + d4];
            sK[k * 65 + d4 + 0] = v.x; sK[k * 65 + d4 + 1] = v.y;
            sK[k * 65 + d4 + 2] = v.z; sK[k * 65 + d4 + 3] = v.w;
        }
        for (int i = t; i < TQ * 64; i += 256) {
            int q = i >> 6, k = i & 63;
            sArc[q * 512 + kt * 64 + k] =
                (unsigned char)arc[((size_t)(b * 512 + q0 + q)) * 512 + kt * 64 + k];
        }
        __syncthreads();
        float acc[4][2] = {};
        #pragma unroll 16
        for (int d = 0; d < 64; d++) {
            float b0 = sK[l * 65 + d];
            float b1 = sK[(l + 32) * 65 + d];
            #pragma unroll
            for (int i = 0; i < 4; i++) {
                float a = sQ[(qb + i) * 64 + d];
                acc[i][0] += a * b0;
                acc[i][1] += a * b1;
            }
        }
        #pragma unroll
        for (int i = 0; i < 4; i++) {
            int q = qb + i;
            #pragma unroll
            for (int j = 0; j < 2; j++) {
                int kg = kt * 64 + l + j * 32;
                float s = acc[i][j] * 0.125f + sQdp[(q << 2) + sArc[q * 512 + kg]] + sMask[kg];
                sS[q * 512 + kg] = s;
            }
        }
    }
    __syncthreads();

    // ---- Pass 2: softmax per row + per-arc mass (unnormalized) ----
    int w = t >> 5;
    for (int ri = 0; ri < 4; ri++) {
        int q = w * 4 + ri;
        float mx = -1e30f;
        for (int c = l; c < 512; c += 32) mx = fmaxf(mx, sS[q * 512 + c]);
        #pragma unroll
        for (int o = 16; o; o >>= 1) mx = fmaxf(mx, __shfl_xor_sync(0xffffffffu, mx, o));
        float sum = 0.f, p0 = 0.f, p1 = 0.f, p2 = 0.f;
        for (int c = l; c < 512; c += 32) {
            float p = __expf(sS[q * 512 + c] - mx);
            sS[q * 512 + c] = p;
            sum += p;
            int a = sArc[q * 512 + c];
            if (a == 0) p0 += p; else if (a == 1) p1 += p; else p2 += p;
        }
        #pragma unroll
        for (int o = 16; o; o >>= 1) {
            sum += __shfl_xor_sync(0xffffffffu, sum, o);
            p0  += __shfl_xor_sync(0xffffffffu, p0, o);
            p1  += __shfl_xor_sync(0xffffffffu, p1, o);
            p2  += __shfl_xor_sync(0xffffffffu, p2, o);
        }
        if (l == 0) {
            sInv[q] = 1.f / sum;
            sPw[q * 4 + 0] = p0; sPw[q * 4 + 1] = p1; sPw[q * 4 + 2] = p2;
        }
    }

    // ---- Pass 3: O = P @ V (+ pw @ lnv, * 1/sum) ----
    float oacc[4][2] = {};
    for (int kt = 0; kt < 8; kt++) {
        __syncthreads();
        for (int i = t; i < 64 * 16; i += 256) {
            int k = i >> 4, d4 = (i & 15) << 2;
            float4 v = *(const float4*)&Vbase[(size_t)(kt * 64 + k) * 64 + d4];
            sK[k * 65 + d4 + 0] = v.x; sK[k * 65 + d4 + 1] = v.y;
            sK[k * 65 + d4 + 2] = v.z; sK[k * 65 + d4 + 3] = v.w;
        }
        __syncthreads();
        #pragma unroll 8
        for (int kk = 0; kk < 64; kk++) {
            float v0 = sK[kk * 65 + l];
            float v1 = sK[kk * 65 + l + 32];
            #pragma unroll
            for (int i = 0; i < 4; i++) {
                float p = sS[(qb + i) * 512 + kt * 64 + kk];
                oacc[i][0] += p * v0;
                oacc[i][1] += p * v1;
            }
        }
    }
    #pragma unroll
    for (int i = 0; i < 4; i++) {
        int q = qb + i;
        float inv = sInv[q];
        float pw0 = sPw[q * 4 + 0], pw1 = sPw[q * 4 + 1], pw2 = sPw[q * 4 + 2];
        #pragma unroll
        for (int j = 0; j < 2; j++) {
            int d = l + j * 32;
            float extra = pw0 * g_lnv[d] + pw1 * g_lnv[64 + d] + pw2 * g_lnv[128 + d];
            out[(size_t)(b * 512 + q0 + q) * 768 + h * 64 + d] = (oacc[i][j] + extra) * inv;
        }
    }
}

// ---------------- launcher ----------------------------------------------------
extern "C" void kernel_launch(void* const* d_in, const int* in_sizes, int n_in,
                              void* d_out, int out_size) {
    const float* hidden = (const float*)d_in[0];
    const float* ctx    = (const float*)d_in[1];
    const float* mask   = (const float*)d_in[2];
    const int*   arc    = (const int*)d_in[3];
    const float* Wq = (const float*)d_in[4];  const float* bq = (const float*)d_in[5];
    const float* Wk = (const float*)d_in[6];  const float* bk = (const float*)d_in[7];
    const float* Wv = (const float*)d_in[8];  const float* bv = (const float*)d_in[9];
    const float* dpk = (const float*)d_in[10]; const float* dpv = (const float*)d_in[11];
    const float* lkg = (const float*)d_in[12]; const float* lkb = (const float*)d_in[13];
    const float* lvg = (const float*)d_in[14]; const float* lvb = (const float*)d_in[15];
    float* out = (float*)d_out;

    ln_prep_kernel<<<1, 192>>>(dpk, dpv, lkg, lkb, lvg, lvb);
    qkv_gemm_kernel<<<dim3(12, 32, 3), 256>>>(hidden, ctx, Wq, bq, Wk, bk, Wv, bv);
    qdp_kernel<<<3072, 256>>>();

    cudaFuncSetAttribute(attn_kernel, cudaFuncAttributeMaxDynamicSharedMemorySize,
                         ATTN_SMEM_BYTES);
    attn_kernel<<<dim3(16, 48), 256, ATTN_SMEM_BYTES>>>(mask, arc, out);
}

// round 2
// speedup vs baseline: 1.1219x; 1.1219x over previous
#include <cuda_runtime.h>

#define HNUM 12
#define DHEAD 64
#define BATCH 4
#define LQ 512
#define LK 512
#define DMODEL 768

// ---------------- scratch (device globals; no runtime alloc) ----------------
__device__ float g_Q[BATCH*HNUM*LQ*DHEAD];
__device__ float g_K[BATCH*HNUM*LK*DHEAD];
__device__ float g_V[BATCH*HNUM*LK*DHEAD];
__device__ float g_lnk[3*DHEAD];
__device__ float g_lnv[3*DHEAD];

// ---------------- K1: layernorm the 3+3 relation embedding rows -------------
__global__ void ln_prep_kernel(const float* __restrict__ dpk, const float* __restrict__ dpv,
                               const float* __restrict__ kg, const float* __restrict__ kb,
                               const float* __restrict__ vg, const float* __restrict__ vb) {
    int w = threadIdx.x >> 5;
    int lane = threadIdx.x & 31;
    if (w >= 6) return;
    const float* src = (w < 3) ? dpk + w * DHEAD : dpv + (w - 3) * DHEAD;
    const float* g   = (w < 3) ? kg : vg;
    const float* be  = (w < 3) ? kb : vb;
    float* dst       = (w < 3) ? g_lnk + w * DHEAD : g_lnv + (w - 3) * DHEAD;
    float e0 = src[lane], e1 = src[lane + 32];
    float s = e0 + e1;
    #pragma unroll
    for (int o = 16; o; o >>= 1) s += __shfl_xor_sync(0xffffffffu, s, o);
    float mu = s * (1.0f / 64.0f);
    float d0 = e0 - mu, d1 = e1 - mu;
    float v = d0 * d0 + d1 * d1;
    #pragma unroll
    for (int o = 16; o; o >>= 1) v += __shfl_xor_sync(0xffffffffu, v, o);
    float rs = rsqrtf(v * (1.0f / 64.0f) + 1e-5f);
    dst[lane]      = d0 * rs * g[lane]      + be[lane];
    dst[lane + 32] = d1 * rs * g[lane + 32] + be[lane + 32];
}

// ---------------- K2: QKV projection GEMMs -----------------------------------
__global__ __launch_bounds__(256) void qkv_gemm_kernel(
    const float* __restrict__ hidden, const float* __restrict__ ctx,
    const float* __restrict__ Wq, const float* __restrict__ bq,
    const float* __restrict__ Wk, const float* __restrict__ bk,
    const float* __restrict__ Wv, const float* __restrict__ bv) {
    __shared__ float As[64][16];
    __shared__ float Bs[16][64];
    int sel = blockIdx.z;
    const float* X    = (sel == 0) ? hidden : ctx;
    const float* W    = (sel == 0) ? Wq : (sel == 1 ? Wk : Wv);
    const float* bias = (sel == 0) ? bq : (sel == 1 ? bk : bv);
    float* Out        = (sel == 0) ? g_Q : (sel == 1 ? g_K : g_V);

    int head = blockIdx.x;
    int m0 = blockIdx.y * 64;
    int n0 = head * 64;
    int t = threadIdx.x;

    int ar = t >> 2;
    int ak = (t & 3) << 2;
    int bkk = t >> 4;
    int bc = (t & 15) << 2;
    int row_base = (t >> 4) << 2;
    int col_base = (t & 15) << 2;

    float acc[4][4] = {};
    for (int k0 = 0; k0 < DMODEL; k0 += 16) {
        float4 av = *(const float4*)&X[(size_t)(m0 + ar) * DMODEL + k0 + ak];
        *(float4*)&As[ar][ak] = av;
        float4 bw = *(const float4*)&W[(size_t)(k0 + bkk) * DMODEL + n0 + bc];
        *(float4*)&Bs[bkk][bc] = bw;
        __syncthreads();
        #pragma unroll
        for (int kk = 0; kk < 16; kk++) {
            float4 b4 = *(float4*)&Bs[kk][col_base];
            float a0 = As[row_base + 0][kk];
            float a1 = As[row_base + 1][kk];
            float a2 = As[row_base + 2][kk];
            float a3 = As[row_base + 3][kk];
            acc[0][0] += a0 * b4.x; acc[0][1] += a0 * b4.y; acc[0][2] += a0 * b4.z; acc[0][3] += a0 * b4.w;
            acc[1][0] += a1 * b4.x; acc[1][1] += a1 * b4.y; acc[1][2] += a1 * b4.z; acc[1][3] += a1 * b4.w;
            acc[2][0] += a2 * b4.x; acc[2][1] += a2 * b4.y; acc[2][2] += a2 * b4.z; acc[2][3] += a2 * b4.w;
            acc[3][0] += a3 * b4.x; acc[3][1] += a3 * b4.y; acc[3][2] += a3 * b4.z; acc[3][3] += a3 * b4.w;
        }
        __syncthreads();
    }
    #pragma unroll
    for (int i = 0; i < 4; i++) {
        int m = m0 + row_base + i;
        int bb = m >> 9, l = m & 511;
        float* orow = Out + ((size_t)(bb * HNUM + head) * 512 + l) * DHEAD;
        #pragma unroll
        for (int j = 0; j < 4; j++)
            orow[col_base + j] = acc[i][j] + bias[n0 + col_base + j];
    }
}

// ---------------- K3: fused flash attention with arc relation terms ----------
// grid (16 q-tiles, 48 bh), 256 threads (8 warps), TQ=32; each warp owns 4 rows.
#define TQ 32
#define ATTN_SMEM_BYTES ((TQ*64 + 64*65 + 64*65 + TQ*64 + 512 + TQ*4) * 4 + TQ*64)

__global__ __launch_bounds__(256, 3) void attn_kernel(
    const float* __restrict__ mask, const int* __restrict__ arc,
    float* __restrict__ out) {
    extern __shared__ char smem_raw[];
    float* sQ    = (float*)smem_raw;        // TQ*64
    float* sK    = sQ + TQ * 64;            // 64*65 padded
    float* sV    = sK + 64 * 65;            // 64*65 padded
    float* sP    = sV + 64 * 65;            // TQ*64 probs tile
    float* sMask = sP + TQ * 64;            // 512
    float* sQdp  = sMask + 512;             // TQ*4
    unsigned char* sArc = (unsigned char*)(sQdp + TQ * 4);  // TQ*64 per tile

    int bh = blockIdx.y;
    int b = bh / HNUM, h = bh % HNUM;
    int q0 = blockIdx.x * TQ;
    int t = threadIdx.x;
    int w = t >> 5;
    int l = t & 31;
    int qb = w << 2;   // this warp's 4 query rows: qb..qb+3

    const float* Qbase = g_Q + ((size_t)bh * 512 + q0) * 64;
    const float* Kbase = g_K + (size_t)bh * 512 * 64;
    const float* Vbase = g_V + (size_t)bh * 512 * 64;
    const int*   Abase = arc + ((size_t)b * 512 + q0) * 512;

    for (int i = t; i < TQ * 16; i += 256) {
        int q = i >> 4, d4 = (i & 15) << 2;
        *(float4*)&sQ[q * 64 + d4] = *(const float4*)&Qbase[q * 64 + d4];
    }
    for (int i = t; i < 512; i += 256) sMask[i] = mask[b * 512 + i];
    __syncthreads();

    // qdp for own rows: q . lnk[r]   (warp-local; no sync needed afterwards
    // since phase 1 reads sQdp only for this warp's own rows)
    #pragma unroll
    for (int i = 0; i < 4; i++) {
        int q = qb + i;
        float q0v = sQ[q * 64 + l], q1v = sQ[q * 64 + l + 32];
        float s0 = q0v * g_lnk[l]       + q1v * g_lnk[l + 32];
        float s1 = q0v * g_lnk[64 + l]  + q1v * g_lnk[96 + l];
        float s2 = q0v * g_lnk[128 + l] + q1v * g_lnk[160 + l];
        #pragma unroll
        for (int o = 16; o; o >>= 1) {
            s0 += __shfl_xor_sync(0xffffffffu, s0, o);
            s1 += __shfl_xor_sync(0xffffffffu, s1, o);
            s2 += __shfl_xor_sync(0xffffffffu, s2, o);
        }
        if (l == 0) {
            sQdp[q * 4 + 0] = s0; sQdp[q * 4 + 1] = s1;
            sQdp[q * 4 + 2] = s2; sQdp[q * 4 + 3] = 0.f;
        }
        __syncwarp();
    }

    // online-softmax state (per-lane partials for sum/pw; m is warp-uniform)
    float m_run[4], rsum[4], pw[4][3], oacc[4][2];
    #pragma unroll
    for (int i = 0; i < 4; i++) {
        m_run[i] = -1e30f; rsum[i] = 0.f;
        pw[i][0] = pw[i][1] = pw[i][2] = 0.f;
        oacc[i][0] = oacc[i][1] = 0.f;
    }

    for (int kt = 0; kt < 8; kt++) {
        __syncthreads();
        // load K tile, V tile (padded 65), arc tile (bytes)
        for (int i = t; i < 64 * 16; i += 256) {
            int k = i >> 4, d4 = (i & 15) << 2;
            float4 kv = *(const float4*)&Kbase[(size_t)(kt * 64 + k) * 64 + d4];
            sK[k * 65 + d4 + 0] = kv.x; sK[k * 65 + d4 + 1] = kv.y;
            sK[k * 65 + d4 + 2] = kv.z; sK[k * 65 + d4 + 3] = kv.w;
            float4 vv = *(const float4*)&Vbase[(size_t)(kt * 64 + k) * 64 + d4];
            sV[k * 65 + d4 + 0] = vv.x; sV[k * 65 + d4 + 1] = vv.y;
            sV[k * 65 + d4 + 2] = vv.z; sV[k * 65 + d4 + 3] = vv.w;
        }
        for (int i = t; i < TQ * 64; i += 256) {
            int q = i >> 6, k = i & 63;
            sArc[q * 64 + k] = (unsigned char)Abase[(size_t)q * 512 + kt * 64 + k];
        }
        __syncthreads();

        // scores for this warp's 4 rows x 64 keys (lane l covers keys l, l+32)
        float acc[4][2] = {};
        #pragma unroll 16
        for (int d = 0; d < 64; d++) {
            float b0 = sK[l * 65 + d];
            float b1 = sK[(l + 32) * 65 + d];
            #pragma unroll
            for (int i = 0; i < 4; i++) {
                float a = sQ[(qb + i) * 64 + d];
                acc[i][0] += a * b0;
                acc[i][1] += a * b1;
            }
        }

        float scale_r[4];
        #pragma unroll
        for (int i = 0; i < 4; i++) {
            int q = qb + i;
            int a0 = sArc[q * 64 + l], a1 = sArc[q * 64 + l + 32];
            float s0 = acc[i][0] * 0.125f + sQdp[q * 4 + a0] + sMask[kt * 64 + l];
            float s1 = acc[i][1] * 0.125f + sQdp[q * 4 + a1] + sMask[kt * 64 + l + 32];
            float tm = fmaxf(s0, s1);
            #pragma unroll
            for (int o = 16; o; o >>= 1) tm = fmaxf(tm, __shfl_xor_sync(0xffffffffu, tm, o));
            float nm = fmaxf(m_run[i], tm);
            float scale = __expf(m_run[i] - nm);
            m_run[i] = nm;
            scale_r[i] = scale;
            float p0 = __expf(s0 - nm);
            float p1 = __expf(s1 - nm);
            sP[q * 64 + l] = p0;
            sP[q * 64 + l + 32] = p1;
            // per-lane running partials (reduced once at the end)
            rsum[i] = rsum[i] * scale + p0 + p1;
            pw[i][0] = pw[i][0] * scale + (a0 == 0 ? p0 : 0.f) + (a1 == 0 ? p1 : 0.f);
            pw[i][1] = pw[i][1] * scale + (a0 == 1 ? p0 : 0.f) + (a1 == 1 ? p1 : 0.f);
            pw[i][2] = pw[i][2] * scale + (a0 == 2 ? p0 : 0.f) + (a1 == 2 ? p1 : 0.f);
        }
        __syncwarp();

        // P @ V for own rows (lane l covers dims l, l+32); sP is warp-private rows
        #pragma unroll
        for (int i = 0; i < 4; i++) {
            oacc[i][0] *= scale_r[i];
            oacc[i][1] *= scale_r[i];
        }
        #pragma unroll 8
        for (int kk = 0; kk < 64; kk++) {
            float v0 = sV[kk * 65 + l];
            float v1 = sV[kk * 65 + l + 32];
            #pragma unroll
            for (int i = 0; i < 4; i++) {
                float p = sP[(qb + i) * 64 + kk];
                oacc[i][0] += p * v0;
                oacc[i][1] += p * v1;
            }
        }
    }

    // final reductions + output
    #pragma unroll
    for (int i = 0; i < 4; i++) {
        int q = qb + i;
        float su = rsum[i], c0 = pw[i][0], c1 = pw[i][1], c2 = pw[i][2];
        #pragma unroll
        for (int o = 16; o; o >>= 1) {
            su += __shfl_xor_sync(0xffffffffu, su, o);
            c0 += __shfl_xor_sync(0xffffffffu, c0, o);
            c1 += __shfl_xor_sync(0xffffffffu, c1, o);
            c2 += __shfl_xor_sync(0xffffffffu, c2, o);
        }
        float inv = 1.f / su;
        #pragma unroll
        for (int j = 0; j < 2; j++) {
            int d = l + j * 32;
            float extra = c0 * g_lnv[d] + c1 * g_lnv[64 + d] + c2 * g_lnv[128 + d];
            out[(size_t)(b * 512 + q0 + q) * 768 + h * 64 + d] = (oacc[i][j] + extra) * inv;
        }
    }
}

// ---------------- launcher ----------------------------------------------------
extern "C" void kernel_launch(void* const* d_in, const int* in_sizes, int n_in,
                              void* d_out, int out_size) {
    const float* hidden = (const float*)d_in[0];
    const float* ctx    = (const float*)d_in[1];
    const float* mask   = (const float*)d_in[2];
    const int*   arc    = (const int*)d_in[3];
    const float* Wq = (const float*)d_in[4];  const float* bq = (const float*)d_in[5];
    const float* Wk = (const float*)d_in[6];  const float* bk = (const float*)d_in[7];
    const float* Wv = (const float*)d_in[8];  const float* bv = (const float*)d_in[9];
    const float* dpk = (const float*)d_in[10]; const float* dpv = (const float*)d_in[11];
    const float* lkg = (const float*)d_in[12]; const float* lkb = (const float*)d_in[13];
    const float* lvg = (const float*)d_in[14]; const float* lvb = (const float*)d_in[15];
    float* out = (float*)d_out;

    ln_prep_kernel<<<1, 192>>>(dpk, dpv, lkg, lkb, lvg, lvb);
    qkv_gemm_kernel<<<dim3(12, 32, 3), 256>>>(hidden, ctx, Wq, bq, Wk, bk, Wv, bv);

    cudaFuncSetAttribute(attn_kernel, cudaFuncAttributeMaxDynamicSharedMemorySize,
                         ATTN_SMEM_BYTES);
    attn_kernel<<<dim3(16, 48), 256, ATTN_SMEM_BYTES>>>(mask, arc, out);
}

// round 4
// speedup vs baseline: 1.9146x; 1.7066x over previous
#include <cuda_runtime.h>
#include <cstdint>

#define HNUM 12
#define DHEAD 64
#define BATCH 4
#define LQ 512
#define LK 512
#define DMODEL 768

// ---------------- scratch (device globals; no runtime alloc) ----------------
__device__ float g_Q[BATCH*HNUM*LQ*DHEAD];
__device__ float g_K[BATCH*HNUM*LK*DHEAD];
__device__ float g_V[BATCH*HNUM*LK*DHEAD];
__device__ float g_lnk[3*DHEAD];
__device__ float g_lnv[3*DHEAD];

// ---------------- K1: layernorm the 3+3 relation embedding rows -------------
__global__ void ln_prep_kernel(const float* __restrict__ dpk, const float* __restrict__ dpv,
                               const float* __restrict__ kg, const float* __restrict__ kb,
                               const float* __restrict__ vg, const float* __restrict__ vb) {
    int w = threadIdx.x >> 5;
    int lane = threadIdx.x & 31;
    if (w >= 6) return;
    const float* src = (w < 3) ? dpk + w * DHEAD : dpv + (w - 3) * DHEAD;
    const float* g   = (w < 3) ? kg : vg;
    const float* be  = (w < 3) ? kb : vb;
    float* dst       = (w < 3) ? g_lnk + w * DHEAD : g_lnv + (w - 3) * DHEAD;
    float e0 = src[lane], e1 = src[lane + 32];
    float s = e0 + e1;
    #pragma unroll
    for (int o = 16; o; o >>= 1) s += __shfl_xor_sync(0xffffffffu, s, o);
    float mu = s * (1.0f / 64.0f);
    float d0 = e0 - mu, d1 = e1 - mu;
    float v = d0 * d0 + d1 * d1;
    #pragma unroll
    for (int o = 16; o; o >>= 1) v += __shfl_xor_sync(0xffffffffu, v, o);
    float rs = rsqrtf(v * (1.0f / 64.0f) + 1e-5f);
    dst[lane]      = d0 * rs * g[lane]      + be[lane];
    dst[lane + 32] = d1 * rs * g[lane + 32] + be[lane + 32];
}

// ---------------- K2: tf32 mma.sync QKV GEMM ---------------------------------
// grid (16 m-tiles of 128, 6 n-tiles of 128, 3 matrices), 256 threads.
// A tile smem [128][36] (row-major, pad->stride 36 == 4 mod 32: conflict-free frags)
// B tile smem [32][132]  (k-major, W native layout; stride 132 == 4 mod 32)
#define A_STRIDE 36
#define B_STRIDE 132
#define STAGE_FLOATS (128 * A_STRIDE + 32 * B_STRIDE)      // 4608 + 4224 = 8832
#define GEMM_SMEM_BYTES (2 * STAGE_FLOATS * 4)             // 70656

#define CP_ASYNC16(dst, src) \
    asm volatile("cp.async.cg.shared.global [%0], [%1], 16;" :: "r"(dst), "l"(src) : "memory")
#define CP_COMMIT() asm volatile("cp.async.commit_group;" ::: "memory")
#define CP_WAIT1()  asm volatile("cp.async.wait_group 1;" ::: "memory")
#define CP_WAIT0()  asm volatile("cp.async.wait_group 0;" ::: "memory")

#define MMA_TF32(d, a, b)                                                     \
    asm volatile("mma.sync.aligned.m16n8k8.row.col.f32.tf32.tf32.f32 "         \
        "{%0,%1,%2,%3}, {%4,%5,%6,%7}, {%8,%9}, {%0,%1,%2,%3};"                \
        : "+f"((d)[0]), "+f"((d)[1]), "+f"((d)[2]), "+f"((d)[3])               \
        : "r"(__float_as_uint((a)[0])), "r"(__float_as_uint((a)[1])),          \
          "r"(__float_as_uint((a)[2])), "r"(__float_as_uint((a)[3])),          \
          "r"(__float_as_uint((b)[0])), "r"(__float_as_uint((b)[1])))

__global__ __launch_bounds__(256, 2) void qkv_gemm_mma_kernel(
    const float* __restrict__ hidden, const float* __restrict__ ctx,
    const float* __restrict__ Wq, const float* __restrict__ bq,
    const float* __restrict__ Wk, const float* __restrict__ bk,
    const float* __restrict__ Wv, const float* __restrict__ bv) {
    extern __shared__ float smem[];

    int sel = blockIdx.z;
    const float* X    = (sel == 0) ? hidden : ctx;
    const float* W    = (sel == 0) ? Wq : (sel == 1 ? Wk : Wv);
    const float* bias = (sel == 0) ? bq : (sel == 1 ? bk : bv);
    float* Out        = (sel == 0) ? g_Q : (sel == 1 ? g_K : g_V);

    int m0 = blockIdx.x * 128;
    int n0 = blockIdx.y * 128;
    int t = threadIdx.x;
    int w = t >> 5;
    int lane = t & 31;
    int gid = lane >> 2;     // 0..7
    int tid4 = lane & 3;     // 0..3
    int wm = w >> 2;         // 0..1 -> 64-row slab
    int wn = w & 3;          // 0..3 -> 32-col slab

    // async-load chunk c (k0 = c*32) into stage s
    auto load_chunk = [&](int c, int s) {
        int k0 = c * 32;
        float* sA = smem + s * STAGE_FLOATS;
        float* sB = sA + 128 * A_STRIDE;
        #pragma unroll
        for (int it = 0; it < 4; it++) {           // A: 128 rows x 8 float4
            int idx = it * 256 + t;
            int r = idx >> 3, c4 = (idx & 7) << 2;
            uint32_t dst = (uint32_t)__cvta_generic_to_shared(&sA[r * A_STRIDE + c4]);
            CP_ASYNC16(dst, &X[(size_t)(m0 + r) * DMODEL + k0 + c4]);
        }
        #pragma unroll
        for (int it = 0; it < 4; it++) {           // B: 32 k-rows x 32 float4
            int idx = it * 256 + t;
            int kr = idx >> 5, c4 = (idx & 31) << 2;
            uint32_t dst = (uint32_t)__cvta_generic_to_shared(&sB[kr * B_STRIDE + c4]);
            CP_ASYNC16(dst, &W[(size_t)(k0 + kr) * DMODEL + n0 + c4]);
        }
        CP_COMMIT();
    };

    float acc[4][4][4];                            // [mt][nt][frag]
    #pragma unroll
    for (int mt = 0; mt < 4; mt++)
        #pragma unroll
        for (int nt = 0; nt < 4; nt++)
            #pragma unroll
            for (int f = 0; f < 4; f++) acc[mt][nt][f] = 0.f;

    load_chunk(0, 0);
    load_chunk(1, 1);
    CP_WAIT1();
    __syncthreads();

    for (int c = 0; c < 24; c++) {
        int s = c & 1;
        const float* sA = smem + s * STAGE_FLOATS;
        const float* sB = sA + 128 * A_STRIDE;
        #pragma unroll
        for (int ks = 0; ks < 4; ks++) {
            int k = ks * 8 + tid4;
            float afr[4][4];
            #pragma unroll
            for (int mt = 0; mt < 4; mt++) {
                int r = wm * 64 + mt * 16 + gid;
                afr[mt][0] = sA[r * A_STRIDE + k];
                afr[mt][1] = sA[(r + 8) * A_STRIDE + k];
                afr[mt][2] = sA[r * A_STRIDE + k + 4];
                afr[mt][3] = sA[(r + 8) * A_STRIDE + k + 4];
            }
            #pragma unroll
            for (int nt = 0; nt < 4; nt++) {
                int n = wn * 32 + nt * 8 + gid;
                float bfr[2];
                bfr[0] = sB[k * B_STRIDE + n];
                bfr[1] = sB[(k + 4) * B_STRIDE + n];
                #pragma unroll
                for (int mt = 0; mt < 4; mt++)
                    MMA_TF32(acc[mt][nt], afr[mt], bfr);
            }
        }
        __syncthreads();
        if (c + 2 < 24) {
            load_chunk(c + 2, s);
            CP_WAIT1();
        } else {
            CP_WAIT0();
        }
        __syncthreads();
    }

    // epilogue: bias + scatter to [B,H,tok,64]
    float bv2[4][2];
    #pragma unroll
    for (int nt = 0; nt < 4; nt++) {
        int col = n0 + wn * 32 + nt * 8 + tid4 * 2;
        bv2[nt][0] = bias[col];
        bv2[nt][1] = bias[col + 1];
    }
    #pragma unroll
    for (int mt = 0; mt < 4; mt++) {
        #pragma unroll
        for (int half = 0; half < 2; half++) {
            int row = m0 + wm * 64 + mt * 16 + gid + half * 8;
            int b = row >> 9, tok = row & 511;
            #pragma unroll
            for (int nt = 0; nt < 4; nt++) {
                int col = n0 + wn * 32 + nt * 8 + tid4 * 2;
                int head = col >> 6, dh = col & 63;
                float2 v;
                v.x = acc[mt][nt][half * 2 + 0] + bv2[nt][0];
                v.y = acc[mt][nt][half * 2 + 1] + bv2[nt][1];
                *(float2*)&Out[((size_t)(b * HNUM + head) * 512 + tok) * 64 + dh] = v;
            }
        }
    }
}

// ---------------- K3: fused flash attention with arc relation terms ----------
#define TQ 32
#define ATTN_SMEM_BYTES ((TQ*64 + 64*65 + 64*65 + TQ*64 + 512 + TQ*4) * 4 + TQ*64)

__global__ __launch_bounds__(256, 3) void attn_kernel(
    const float* __restrict__ mask, const int* __restrict__ arc,
    float* __restrict__ out) {
    extern __shared__ char smem_raw[];
    float* sQ    = (float*)smem_raw;        // TQ*64
    float* sK    = sQ + TQ * 64;            // 64*65 padded
    float* sV    = sK + 64 * 65;            // 64*65 padded
    float* sP    = sV + 64 * 65;            // TQ*64 probs tile
    float* sMask = sP + TQ * 64;            // 512
    float* sQdp  = sMask + 512;             // TQ*4
    unsigned char* sArc = (unsigned char*)(sQdp + TQ * 4);  // TQ*64 per tile

    int bh = blockIdx.y;
    int b = bh / HNUM, h = bh % HNUM;
    int q0 = blockIdx.x * TQ;
    int t = threadIdx.x;
    int w = t >> 5;
    int l = t & 31;
    int qb = w << 2;

    const float* Qbase = g_Q + ((size_t)bh * 512 + q0) * 64;
    const float* Kbase = g_K + (size_t)bh * 512 * 64;
    const float* Vbase = g_V + (size_t)bh * 512 * 64;
    const int*   Abase = arc + ((size_t)b * 512 + q0) * 512;

    for (int i = t; i < TQ * 16; i += 256) {
        int q = i >> 4, d4 = (i & 15) << 2;
        *(float4*)&sQ[q * 64 + d4] = *(const float4*)&Qbase[q * 64 + d4];
    }
    for (int i = t; i < 512; i += 256) sMask[i] = mask[b * 512 + i];
    __syncthreads();

    #pragma unroll
    for (int i = 0; i < 4; i++) {
        int q = qb + i;
        float q0v = sQ[q * 64 + l], q1v = sQ[q * 64 + l + 32];
        float s0 = q0v * g_lnk[l]       + q1v * g_lnk[l + 32];
        float s1 = q0v * g_lnk[64 + l]  + q1v * g_lnk[96 + l];
        float s2 = q0v * g_lnk[128 + l] + q1v * g_lnk[160 + l];
        #pragma unroll
        for (int o = 16; o; o >>= 1) {
            s0 += __shfl_xor_sync(0xffffffffu, s0, o);
            s1 += __shfl_xor_sync(0xffffffffu, s1, o);
            s2 += __shfl_xor_sync(0xffffffffu, s2, o);
        }
        if (l == 0) {
            sQdp[q * 4 + 0] = s0; sQdp[q * 4 + 1] = s1;
            sQdp[q * 4 + 2] = s2; sQdp[q * 4 + 3] = 0.f;
        }
        __syncwarp();
    }

    float m_run[4], rsum[4], pw[4][3], oacc[4][2];
    #pragma unroll
    for (int i = 0; i < 4; i++) {
        m_run[i] = -1e30f; rsum[i] = 0.f;
        pw[i][0] = pw[i][1] = pw[i][2] = 0.f;
        oacc[i][0] = oacc[i][1] = 0.f;
    }

    for (int kt = 0; kt < 8; kt++) {
        __syncthreads();
        for (int i = t; i < 64 * 16; i += 256) {
            int k = i >> 4, d4 = (i & 15) << 2;
            float4 kv = *(const float4*)&Kbase[(size_t)(kt * 64 + k) * 64 + d4];
            sK[k * 65 + d4 + 0] = kv.x; sK[k * 65 + d4 + 1] = kv.y;
            sK[k * 65 + d4 + 2] = kv.z; sK[k * 65 + d4 + 3] = kv.w;
            float4 vv = *(const float4*)&Vbase[(size_t)(kt * 64 + k) * 64 + d4];
            sV[k * 65 + d4 + 0] = vv.x; sV[k * 65 + d4 + 1] = vv.y;
            sV[k * 65 + d4 + 2] = vv.z; sV[k * 65 + d4 + 3] = vv.w;
        }
        for (int i = t; i < TQ * 64; i += 256) {
            int q = i >> 6, k = i & 63;
            sArc[q * 64 + k] = (unsigned char)Abase[(size_t)q * 512 + kt * 64 + k];
        }
        __syncthreads();

        float acc[4][2] = {};
        #pragma unroll 16
        for (int d = 0; d < 64; d++) {
            float b0 = sK[l * 65 + d];
            float b1 = sK[(l + 32) * 65 + d];
            #pragma unroll
            for (int i = 0; i < 4; i++) {
                float a = sQ[(qb + i) * 64 + d];
                acc[i][0] += a * b0;
                acc[i][1] += a * b1;
            }
        }

        float scale_r[4];
        #pragma unroll
        for (int i = 0; i < 4; i++) {
            int q = qb + i;
            int a0 = sArc[q * 64 + l], a1 = sArc[q * 64 + l + 32];
            float s0 = acc[i][0] * 0.125f + sQdp[q * 4 + a0] + sMask[kt * 64 + l];
            float s1 = acc[i][1] * 0.125f + sQdp[q * 4 + a1] + sMask[kt * 64 + l + 32];
            float tm = fmaxf(s0, s1);
            #pragma unroll
            for (int o = 16; o; o >>= 1) tm = fmaxf(tm, __shfl_xor_sync(0xffffffffu, tm, o));
            float nm = fmaxf(m_run[i], tm);
            float scale = __expf(m_run[i] - nm);
            m_run[i] = nm;
            scale_r[i] = scale;
            float p0 = __expf(s0 - nm);
            float p1 = __expf(s1 - nm);
            sP[q * 64 + l] = p0;
            sP[q * 64 + l + 32] = p1;
            rsum[i] = rsum[i] * scale + p0 + p1;
            pw[i][0] = pw[i][0] * scale + (a0 == 0 ? p0 : 0.f) + (a1 == 0 ? p1 : 0.f);
            pw[i][1] = pw[i][1] * scale + (a0 == 1 ? p0 : 0.f) + (a1 == 1 ? p1 : 0.f);
            pw[i][2] = pw[i][2] * scale + (a0 == 2 ? p0 : 0.f) + (a1 == 2 ? p1 : 0.f);
        }
        __syncwarp();

        #pragma unroll
        for (int i = 0; i < 4; i++) {
            oacc[i][0] *= scale_r[i];
            oacc[i][1] *= scale_r[i];
        }
        #pragma unroll 8
        for (int kk = 0; kk < 64; kk++) {
            float v0 = sV[kk * 65 + l];
            float v1 = sV[kk * 65 + l + 32];
            #pragma unroll
            for (int i = 0; i < 4; i++) {
                float p = sP[(qb + i) * 64 + kk];
                oacc[i][0] += p * v0;
                oacc[i][1] += p * v1;
            }
        }
    }

    #pragma unroll
    for (int i = 0; i < 4; i++) {
        int q = qb + i;
        float su = rsum[i], c0 = pw[i][0], c1 = pw[i][1], c2 = pw[i][2];
        #pragma unroll
        for (int o = 16; o; o >>= 1) {
            su += __shfl_xor_sync(0xffffffffu, su, o);
            c0 += __shfl_xor_sync(0xffffffffu, c0, o);
            c1 += __shfl_xor_sync(0xffffffffu, c1, o);
            c2 += __shfl_xor_sync(0xffffffffu, c2, o);
        }
        float inv = 1.f / su;
        #pragma unroll
        for (int j = 0; j < 2; j++) {
            int d = l + j * 32;
            float extra = c0 * g_lnv[d] + c1 * g_lnv[64 + d] + c2 * g_lnv[128 + d];
            out[(size_t)(b * 512 + q0 + q) * 768 + h * 64 + d] = (oacc[i][j] + extra) * inv;
        }
    }
}

// ---------------- launcher ----------------------------------------------------
extern "C" void kernel_launch(void* const* d_in, const int* in_sizes, int n_in,
                              void* d_out, int out_size) {
    const float* hidden = (const float*)d_in[0];
    const float* ctx    = (const float*)d_in[1];
    const float* mask   = (const float*)d_in[2];
    const int*   arc    = (const int*)d_in[3];
    const float* Wq = (const float*)d_in[4];  const float* bq = (const float*)d_in[5];
    const float* Wk = (const float*)d_in[6];  const float* bk = (const float*)d_in[7];
    const float* Wv = (const float*)d_in[8];  const float* bv = (const float*)d_in[9];
    const float* dpk = (const float*)d_in[10]; const float* dpv = (const float*)d_in[11];
    const float* lkg = (const float*)d_in[12]; const float* lkb = (const float*)d_in[13];
    const float* lvg = (const float*)d_in[14]; const float* lvb = (const float*)d_in[15];
    float* out = (float*)d_out;

    ln_prep_kernel<<<1, 192>>>(dpk, dpv, lkg, lkb, lvg, lvb);

    cudaFuncSetAttribute(qkv_gemm_mma_kernel, cudaFuncAttributeMaxDynamicSharedMemorySize,
                         GEMM_SMEM_BYTES);
    qkv_gemm_mma_kernel<<<dim3(16, 6, 3), 256, GEMM_SMEM_BYTES>>>(
        hidden, ctx, Wq, bq, Wk, bk, Wv, bv);

    cudaFuncSetAttribute(attn_kernel, cudaFuncAttributeMaxDynamicSharedMemorySize,
                         ATTN_SMEM_BYTES);
    attn_kernel<<<dim3(16, 48), 256, ATTN_SMEM_BYTES>>>(mask, arc, out);
}